// round 1
// baseline (speedup 1.0000x reference)
#include <cuda_runtime.h>

#define NLAYER 4
#define TSEQ   34
#define VOCAB  14
#define BSEQ   8
#define NTHR   (BSEQ * TSEQ)   // 272
#define KV_STRIDE 412          // floats per sequence kv buffer (34*12=408 used, padded)
#define LW 104                 // floats per layer weight block
// layer block: [q1w 0..8][k1w 9..17][v1w 18..26][q2w 27..35][k2w 36..44][v2w 45..53]
//              [out_w 54..89][ln_w 90..95][ln_b 96..101][pad 102..103]
#define OFF_LNF_W 416
#define OFF_LNF_B 422
#define OFF_HEAD  428          // 84 floats
#define OFF_TOK   512          // 42 floats
#define OFF_POS   554          // 102 floats
#define W_TOTAL   656

__global__ void __launch_bounds__(NTHR)
addtx_kernel(const int* __restrict__ idx,
             const float* __restrict__ tok_emb, const float* __restrict__ pos_enc,
             const float* __restrict__ ln_w,   const float* __restrict__ ln_b,
             const float* __restrict__ q1w,    const float* __restrict__ k1w,
             const float* __restrict__ v1w,    const float* __restrict__ q2w,
             const float* __restrict__ k2w,    const float* __restrict__ v2w,
             const float* __restrict__ out_w,  const float* __restrict__ lnf_w,
             const float* __restrict__ lnf_b,  const float* __restrict__ head_w,
             float* __restrict__ out)
{
    __shared__ float W[W_TOTAL];
    __shared__ float kv[BSEQ * KV_STRIDE];

    const int s   = threadIdx.x;            // seq within block (0..7)
    const int t   = threadIdx.y;            // token (0..33)
    const int tid = threadIdx.y * BSEQ + threadIdx.x;
    const int b   = blockIdx.x * BSEQ + s;

    // ---- cooperative weight staging into smem ----
    for (int i = tid; i < NLAYER * 9; i += NTHR) {
        int l = i / 9, r = i - l * 9;
        W[l * LW +  0 + r] = q1w[i];
        W[l * LW +  9 + r] = k1w[i];
        W[l * LW + 18 + r] = v1w[i];
        W[l * LW + 27 + r] = q2w[i];
        W[l * LW + 36 + r] = k2w[i];
        W[l * LW + 45 + r] = v2w[i];
    }
    for (int i = tid; i < NLAYER * 36; i += NTHR) {
        int l = i / 36, r = i - l * 36;
        W[l * LW + 54 + r] = out_w[i];
    }
    for (int i = tid; i < NLAYER * 6; i += NTHR) {
        int l = i / 6, r = i - l * 6;
        W[l * LW + 90 + r] = ln_w[i];
        W[l * LW + 96 + r] = ln_b[i];
    }
    if (tid < 6) { W[OFF_LNF_W + tid] = lnf_w[tid]; W[OFF_LNF_B + tid] = lnf_b[tid]; }
    for (int i = tid; i < VOCAB * 6; i += NTHR) W[OFF_HEAD + i] = head_w[i];
    for (int i = tid; i < VOCAB * 3; i += NTHR) W[OFF_TOK + i]  = tok_emb[i];
    for (int i = tid; i < TSEQ * 3; i += NTHR)  W[OFF_POS + i]  = pos_enc[i];
    __syncthreads();

    // ---- embedding ----
    const int tok = idx[b * TSEQ + t];
    float x[6];
    x[0] = W[OFF_TOK + tok * 3 + 0];
    x[1] = W[OFF_TOK + tok * 3 + 1];
    x[2] = W[OFF_TOK + tok * 3 + 2];
    x[3] = W[OFF_POS + t * 3 + 0];
    x[4] = W[OFF_POS + t * 3 + 1];
    x[5] = W[OFF_POS + t * 3 + 2];

    float* mykv = kv + s * KV_STRIDE;
    const float sc = 0.57735026918962576451f;  // 1/sqrt(3)

    #pragma unroll
    for (int l = 0; l < NLAYER; l++) {
        const float* Wl = W + l * LW;

        // layernorm
        float m = (x[0] + x[1] + x[2] + x[3] + x[4] + x[5]) * (1.f / 6.f);
        float var = 0.f;
        float h[6];
        #pragma unroll
        for (int d = 0; d < 6; d++) { float c = x[d] - m; var += c * c; h[d] = c; }
        float inv = rsqrtf(var * (1.f / 6.f) + 1e-5f);
        #pragma unroll
        for (int d = 0; d < 6; d++) h[d] = h[d] * inv * Wl[90 + d] + Wl[96 + d];

        // qkv projections (head1 from h[0..2], head2 from h[3..5])
        float q1[3], k1t[3], v1t[3], q2[3], k2t[3], v2t[3];
        #pragma unroll
        for (int d = 0; d < 3; d++) {
            q1[d]  = Wl[ 0 + d*3] * h[0] + Wl[ 1 + d*3] * h[1] + Wl[ 2 + d*3] * h[2];
            k1t[d] = Wl[ 9 + d*3] * h[0] + Wl[10 + d*3] * h[1] + Wl[11 + d*3] * h[2];
            v1t[d] = Wl[18 + d*3] * h[0] + Wl[19 + d*3] * h[1] + Wl[20 + d*3] * h[2];
            q2[d]  = Wl[27 + d*3] * h[3] + Wl[28 + d*3] * h[4] + Wl[29 + d*3] * h[5];
            k2t[d] = Wl[36 + d*3] * h[3] + Wl[37 + d*3] * h[4] + Wl[38 + d*3] * h[5];
            v2t[d] = Wl[45 + d*3] * h[3] + Wl[46 + d*3] * h[4] + Wl[47 + d*3] * h[5];
        }

        // stage k/v for this token (3x float4, 16B aligned)
        float4* p = (float4*)(mykv + t * 12);
        p[0] = make_float4(k1t[0], k1t[1], k1t[2], k2t[0]);
        p[1] = make_float4(k2t[1], k2t[2], v1t[0], v1t[1]);
        p[2] = make_float4(v1t[2], v2t[0], v2t[1], v2t[2]);
        __syncthreads();

        // scaled q
        q1[0] *= sc; q1[1] *= sc; q1[2] *= sc;
        q2[0] *= sc; q2[1] *= sc; q2[2] *= sc;

        // causal attention, no max-subtraction (|s| bounded << 88)
        float sum1 = 0.f, sum2 = 0.f;
        float a1x = 0.f, a1y = 0.f, a1z = 0.f;
        float a2x = 0.f, a2y = 0.f, a2z = 0.f;
        for (int j = 0; j <= t; j++) {
            const float4* pj = (const float4*)(mykv + j * 12);
            float4 A = pj[0], B = pj[1], C = pj[2];
            float s1 = q1[0] * A.x + q1[1] * A.y + q1[2] * A.z;
            float s2 = q2[0] * A.w + q2[1] * B.x + q2[2] * B.y;
            float e1 = __expf(s1);
            float e2 = __expf(s2);
            sum1 += e1; sum2 += e2;
            a1x += e1 * B.z; a1y += e1 * B.w; a1z += e1 * C.x;
            a2x += e2 * C.y; a2y += e2 * C.z; a2z += e2 * C.w;
        }
        float r1 = __fdividef(1.f, sum1);
        float r2 = __fdividef(1.f, sum2);
        float c6[6];
        c6[0] = a1x * r1; c6[1] = a1y * r1; c6[2] = a1z * r1;
        c6[3] = a2x * r2; c6[4] = a2y * r2; c6[5] = a2z * r2;

        // output projection + residual
        #pragma unroll
        for (int d = 0; d < 6; d++) {
            float acc = x[d];
            #pragma unroll
            for (int i = 0; i < 6; i++) acc += Wl[54 + d * 6 + i] * c6[i];
            x[d] = acc;
        }
        __syncthreads();  // protect kv before next layer overwrites
    }

    // final layernorm
    float m = (x[0] + x[1] + x[2] + x[3] + x[4] + x[5]) * (1.f / 6.f);
    float var = 0.f;
    float hf[6];
    #pragma unroll
    for (int d = 0; d < 6; d++) { float c = x[d] - m; var += c * c; hf[d] = c; }
    float inv = rsqrtf(var * (1.f / 6.f) + 1e-5f);
    #pragma unroll
    for (int d = 0; d < 6; d++) hf[d] = hf[d] * inv * W[OFF_LNF_W + d] + W[OFF_LNF_B + d];

    // lm head
    float res[VOCAB];
    #pragma unroll
    for (int v = 0; v < VOCAB; v++) {
        float acc = 0.f;
        #pragma unroll
        for (int d = 0; d < 6; d++) acc += W[OFF_HEAD + v * 6 + d] * hf[d];
        res[v] = acc;
    }

    float2* po = (float2*)(out + ((long)(b * TSEQ + t)) * VOCAB);
    #pragma unroll
    for (int i = 0; i < 7; i++) po[i] = make_float2(res[2 * i], res[2 * i + 1]);
}

extern "C" void kernel_launch(void* const* d_in, const int* in_sizes, int n_in,
                              void* d_out, int out_size)
{
    const int*   idx     = (const int*)d_in[0];
    const float* tok_emb = (const float*)d_in[1];
    const float* pos_enc = (const float*)d_in[2];
    const float* ln_w    = (const float*)d_in[3];
    const float* ln_b    = (const float*)d_in[4];
    const float* q1w     = (const float*)d_in[5];
    const float* k1w     = (const float*)d_in[6];
    const float* v1w     = (const float*)d_in[7];
    const float* q2w     = (const float*)d_in[8];
    const float* k2w     = (const float*)d_in[9];
    const float* v2w     = (const float*)d_in[10];
    const float* out_w   = (const float*)d_in[11];
    const float* lnf_w   = (const float*)d_in[12];
    const float* lnf_b   = (const float*)d_in[13];
    const float* head_w  = (const float*)d_in[14];
    float* out = (float*)d_out;

    const int batch = in_sizes[0] / TSEQ;   // 16384
    dim3 block(BSEQ, TSEQ);
    dim3 grid(batch / BSEQ);
    addtx_kernel<<<grid, block>>>(idx, tok_emb, pos_enc, ln_w, ln_b,
                                  q1w, k1w, v1w, q2w, k2w, v2w,
                                  out_w, lnf_w, lnf_b, head_w, out);
}

// round 2
// speedup vs baseline: 1.6697x; 1.6697x over previous
#include <cuda_runtime.h>

typedef unsigned long long ull;

#define NLAYER 4
#define TSEQ   34
#define VOCAB  14
#define BSEQ   16
#define TROWS  17
#define NTHR   (BSEQ * TROWS)     // 272
#define KV_STRIDE 412             // floats per seq (34*12=408 used, padded for banks)
#define LW 112
// per-layer: WQ pairs [0..17] (pre-scaled), WK pairs [18..35], WV pairs [36..53],
//            WO row-pairs [54..89], ln_w [90..95], ln_b [96..101], pad
#define OFF_LNF_W 448
#define OFF_LNF_B 454
#define OFF_HEAD  460             // 84 floats (7 vocab-pairs x 6)
#define OFF_TOK   544             // 42
#define OFF_POS   586             // 102
#define W_TOTAL   688

__device__ __forceinline__ ull pk(float lo, float hi) {
    ull r; asm("mov.b64 %0,{%1,%2};" : "=l"(r) : "f"(lo), "f"(hi)); return r;
}
__device__ __forceinline__ void upk(ull v, float& lo, float& hi) {
    asm("mov.b64 {%0,%1},%2;" : "=f"(lo), "=f"(hi) : "l"(v));
}
__device__ __forceinline__ ull ffma2(ull a, ull b, ull c) {
    ull d; asm("fma.rn.f32x2 %0,%1,%2,%3;" : "=l"(d) : "l"(a), "l"(b), "l"(c)); return d;
}
__device__ __forceinline__ ull fmul2(ull a, ull b) {
    ull d; asm("mul.rn.f32x2 %0,%1,%2;" : "=l"(d) : "l"(a), "l"(b)); return d;
}
__device__ __forceinline__ ull fadd2(ull a, ull b) {
    ull d; asm("add.rn.f32x2 %0,%1,%2;" : "=l"(d) : "l"(a), "l"(b)); return d;
}
__device__ __forceinline__ float ex2f(float x) {
    float r; asm("ex2.approx.f32 %0,%1;" : "=f"(r) : "f"(x)); return r;
}
__device__ __forceinline__ float rcpf(float x) {
    float r; asm("rcp.approx.f32 %0,%1;" : "=f"(r) : "f"(x)); return r;
}
__device__ __forceinline__ ull exp2pair(ull s) {
    float a, b; upk(s, a, b); return pk(ex2f(a), ex2f(b));
}
__device__ __forceinline__ ull dot2(const ull* q, const ull* k) {
    return ffma2(q[0], k[0], ffma2(q[1], k[1], fmul2(q[2], k[2])));
}

__device__ __forceinline__ void lnorm(const float* x, const float* w, const float* b, float* h) {
    float m = (x[0] + x[1] + x[2] + x[3] + x[4] + x[5]) * (1.f / 6.f);
    float var = 0.f;
    #pragma unroll
    for (int d = 0; d < 6; d++) { float c = x[d] - m; var += c * c; h[d] = c; }
    float inv = rsqrtf(var * (1.f / 6.f) + 1e-5f);
    #pragma unroll
    for (int d = 0; d < 6; d++) h[d] = h[d] * inv * w[d] + b[d];
}

__global__ void __launch_bounds__(NTHR, 3)
addtx_kernel(const int* __restrict__ idx,
             const float* __restrict__ tok_emb, const float* __restrict__ pos_enc,
             const float* __restrict__ ln_w,   const float* __restrict__ ln_b,
             const float* __restrict__ q1w,    const float* __restrict__ k1w,
             const float* __restrict__ v1w,    const float* __restrict__ q2w,
             const float* __restrict__ k2w,    const float* __restrict__ v2w,
             const float* __restrict__ out_w,  const float* __restrict__ lnf_w,
             const float* __restrict__ lnf_b,  const float* __restrict__ head_w,
             float* __restrict__ out)
{
    __shared__ __align__(16) float W[W_TOTAL];
    __shared__ __align__(16) float kv[BSEQ * KV_STRIDE];

    const int s   = threadIdx.x;        // seq in block 0..15
    const int ty  = threadIdx.y;        // token-pair row 0..16
    const int tid = ty * BSEQ + s;
    const int b   = blockIdx.x * BSEQ + s;
    const int ta  = 2 * ty, tb = 2 * ty + 1;

    // ---- stage weights as (head1, head2) pairs ----
    const float SCL = 0.83298066476f;   // (1/sqrt(3)) * log2(e), folded into q weights
    for (int i = tid; i < NLAYER * 9; i += NTHR) {
        int l = i / 9, r = i - l * 9;
        float* Wl = W + l * LW;
        Wl[     2 * r    ] = q1w[i] * SCL;
        Wl[     2 * r + 1] = q2w[i] * SCL;
        Wl[18 + 2 * r    ] = k1w[i];
        Wl[18 + 2 * r + 1] = k2w[i];
        Wl[36 + 2 * r    ] = v1w[i];
        Wl[36 + 2 * r + 1] = v2w[i];
    }
    for (int i = tid; i < NLAYER * 18; i += NTHR) {
        int l = i / 18, p = i - l * 18, dp = p / 6, col = p - dp * 6;
        W[l * LW + 54 + 2 * p    ] = out_w[l * 36 + (2 * dp    ) * 6 + col];
        W[l * LW + 54 + 2 * p + 1] = out_w[l * 36 + (2 * dp + 1) * 6 + col];
    }
    for (int i = tid; i < NLAYER * 6; i += NTHR) {
        int l = i / 6, r = i - l * 6;
        W[l * LW + 90 + r] = ln_w[i];
        W[l * LW + 96 + r] = ln_b[i];
    }
    if (tid < 6) { W[OFF_LNF_W + tid] = lnf_w[tid]; W[OFF_LNF_B + tid] = lnf_b[tid]; }
    for (int i = tid; i < 42; i += NTHR) {          // 7 vocab-pairs x 6 dims
        int vp = i / 6, d = i - vp * 6;
        W[OFF_HEAD + 2 * i    ] = head_w[(2 * vp    ) * 6 + d];
        W[OFF_HEAD + 2 * i + 1] = head_w[(2 * vp + 1) * 6 + d];
    }
    for (int i = tid; i < VOCAB * 3; i += NTHR) W[OFF_TOK + i] = tok_emb[i];
    for (int i = tid; i < TSEQ * 3; i += NTHR)  W[OFF_POS + i] = pos_enc[i];
    __syncthreads();

    // ---- embeddings for both owned tokens ----
    const int tok_a = idx[b * TSEQ + ta];
    const int tok_b = idx[b * TSEQ + tb];
    float xa[6], xb[6];
    #pragma unroll
    for (int d = 0; d < 3; d++) {
        xa[d]     = W[OFF_TOK + tok_a * 3 + d];
        xa[d + 3] = W[OFF_POS + ta * 3 + d];
        xb[d]     = W[OFF_TOK + tok_b * 3 + d];
        xb[d + 3] = W[OFF_POS + tb * 3 + d];
    }

    ulonglong2* kvw = (ulonglong2*)(kv + s * KV_STRIDE);
    const ulonglong2* kvr = kvw;

    #pragma unroll
    for (int l = 0; l < NLAYER; l++) {
        const float* Wl = W + l * LW;
        const ull* WQ = (const ull*)(Wl);
        const ull* WK = (const ull*)(Wl + 18);
        const ull* WV = (const ull*)(Wl + 36);
        const ull* WO = (const ull*)(Wl + 54);

        float ha[6], hb[6];
        lnorm(xa, Wl + 90, Wl + 96, ha);
        lnorm(xb, Wl + 90, Wl + 96, hb);

        ull hpa[3] = { pk(ha[0], ha[3]), pk(ha[1], ha[4]), pk(ha[2], ha[5]) };
        ull hpb[3] = { pk(hb[0], hb[3]), pk(hb[1], hb[4]), pk(hb[2], hb[5]) };

        ull qa[3], ka[3], va[3], qb[3], kb[3], vb[3];
        #pragma unroll
        for (int d = 0; d < 3; d++) {
            ull aq = 0, ak = 0, av = 0, bq = 0, bk = 0, bv = 0;
            #pragma unroll
            for (int e = 0; e < 3; e++) {
                ull wq = WQ[d * 3 + e], wk = WK[d * 3 + e], wv = WV[d * 3 + e];
                aq = ffma2(wq, hpa[e], aq);  bq = ffma2(wq, hpb[e], bq);
                ak = ffma2(wk, hpa[e], ak);  bk = ffma2(wk, hpb[e], bk);
                av = ffma2(wv, hpa[e], av);  bv = ffma2(wv, hpb[e], bv);
            }
            qa[d] = aq; ka[d] = ak; va[d] = av;
            qb[d] = bq; kb[d] = bk; vb[d] = bv;
        }

        // publish k/v (pair-interleaved): {k0,k1},{k2,v0},{v1,v2}
        __syncthreads();                 // prior-layer readers done before overwrite
        kvw[ta * 3 + 0] = make_ulonglong2(ka[0], ka[1]);
        kvw[ta * 3 + 1] = make_ulonglong2(ka[2], va[0]);
        kvw[ta * 3 + 2] = make_ulonglong2(va[1], va[2]);
        kvw[tb * 3 + 0] = make_ulonglong2(kb[0], kb[1]);
        kvw[tb * 3 + 1] = make_ulonglong2(kb[2], vb[0]);
        kvw[tb * 3 + 2] = make_ulonglong2(vb[1], vb[2]);
        __syncthreads();

        // self / cross terms straight from registers (j = ta for a; j = ta, tb for b)
        ull eaa = exp2pair(dot2(qa, ka));
        ull suma = eaa;
        ull aac0 = fmul2(eaa, va[0]), aac1 = fmul2(eaa, va[1]), aac2 = fmul2(eaa, va[2]);

        ull eba = exp2pair(dot2(qb, ka));
        ull ebb = exp2pair(dot2(qb, kb));
        ull sumb = fadd2(eba, ebb);
        ull bac0 = ffma2(eba, va[0], fmul2(ebb, vb[0]));
        ull bac1 = ffma2(eba, va[1], fmul2(ebb, vb[1]));
        ull bac2 = ffma2(eba, va[2], fmul2(ebb, vb[2]));

        // shared causal loop: one kv load serves both query tokens
        #pragma unroll 2
        for (int j = 0; j < ta; j++) {
            ulonglong2 p0 = kvr[j * 3 + 0];
            ulonglong2 p1 = kvr[j * 3 + 1];
            ulonglong2 p2 = kvr[j * 3 + 2];
            ull sa = ffma2(qa[0], p0.x, ffma2(qa[1], p0.y, fmul2(qa[2], p1.x)));
            ull sb = ffma2(qb[0], p0.x, ffma2(qb[1], p0.y, fmul2(qb[2], p1.x)));
            ull ea = exp2pair(sa);
            ull eb = exp2pair(sb);
            suma = fadd2(suma, ea);       sumb = fadd2(sumb, eb);
            aac0 = ffma2(ea, p1.y, aac0); bac0 = ffma2(eb, p1.y, bac0);
            aac1 = ffma2(ea, p2.x, aac1); bac1 = ffma2(eb, p2.x, bac1);
            aac2 = ffma2(ea, p2.y, aac2); bac2 = ffma2(eb, p2.y, bac2);
        }

        // normalize + output projection + residual (both tokens, shared WO loads)
        float sa1, sa2, sb1, sb2;
        upk(suma, sa1, sa2); upk(sumb, sb1, sb2);
        ull ra = pk(rcpf(sa1), rcpf(sa2));
        ull rb = pk(rcpf(sb1), rcpf(sb2));
        float cA[6], cB[6];
        { ull t0 = fmul2(aac0, ra), t1 = fmul2(aac1, ra), t2 = fmul2(aac2, ra);
          upk(t0, cA[0], cA[3]); upk(t1, cA[1], cA[4]); upk(t2, cA[2], cA[5]); }
        { ull t0 = fmul2(bac0, rb), t1 = fmul2(bac1, rb), t2 = fmul2(bac2, rb);
          upk(t0, cB[0], cB[3]); upk(t1, cB[1], cB[4]); upk(t2, cB[2], cB[5]); }
        ull cdA[6], cdB[6];
        #pragma unroll
        for (int i = 0; i < 6; i++) { cdA[i] = pk(cA[i], cA[i]); cdB[i] = pk(cB[i], cB[i]); }
        #pragma unroll
        for (int dp = 0; dp < 3; dp++) {
            ull accA = pk(xa[2 * dp], xa[2 * dp + 1]);
            ull accB = pk(xb[2 * dp], xb[2 * dp + 1]);
            #pragma unroll
            for (int i = 0; i < 6; i++) {
                ull wo = WO[dp * 6 + i];
                accA = ffma2(wo, cdA[i], accA);
                accB = ffma2(wo, cdB[i], accB);
            }
            upk(accA, xa[2 * dp], xa[2 * dp + 1]);
            upk(accB, xb[2 * dp], xb[2 * dp + 1]);
        }
    }

    // ---- final LN + lm head (vocab-pair FFMA2), 8B stores ----
    float hfa[6], hfb[6];
    lnorm(xa, W + OFF_LNF_W, W + OFF_LNF_B, hfa);
    lnorm(xb, W + OFF_LNF_W, W + OFF_LNF_B, hfb);
    ull hda[6], hdb[6];
    #pragma unroll
    for (int d = 0; d < 6; d++) { hda[d] = pk(hfa[d], hfa[d]); hdb[d] = pk(hfb[d], hfb[d]); }

    const ull* WH = (const ull*)(W + OFF_HEAD);
    ull* oa = (ull*)(out + (size_t)(b * TSEQ + ta) * VOCAB);
    ull* ob = (ull*)(out + (size_t)(b * TSEQ + tb) * VOCAB);
    #pragma unroll
    for (int vp = 0; vp < 7; vp++) {
        ull rA = 0, rB = 0;
        #pragma unroll
        for (int d = 0; d < 6; d++) {
            ull wh = WH[vp * 6 + d];
            rA = ffma2(wh, hda[d], rA);
            rB = ffma2(wh, hdb[d], rB);
        }
        oa[vp] = rA;
        ob[vp] = rB;
    }
}

extern "C" void kernel_launch(void* const* d_in, const int* in_sizes, int n_in,
                              void* d_out, int out_size)
{
    const int*   idx     = (const int*)d_in[0];
    const float* tok_emb = (const float*)d_in[1];
    const float* pos_enc = (const float*)d_in[2];
    const float* ln_w    = (const float*)d_in[3];
    const float* ln_b    = (const float*)d_in[4];
    const float* q1w     = (const float*)d_in[5];
    const float* k1w     = (const float*)d_in[6];
    const float* v1w     = (const float*)d_in[7];
    const float* q2w     = (const float*)d_in[8];
    const float* k2w     = (const float*)d_in[9];
    const float* v2w     = (const float*)d_in[10];
    const float* out_w   = (const float*)d_in[11];
    const float* lnf_w   = (const float*)d_in[12];
    const float* lnf_b   = (const float*)d_in[13];
    const float* head_w  = (const float*)d_in[14];
    float* out = (float*)d_out;

    const int batch = in_sizes[0] / TSEQ;      // 16384
    dim3 block(BSEQ, TROWS);
    dim3 grid(batch / BSEQ);
    addtx_kernel<<<grid, block>>>(idx, tok_emb, pos_enc, ln_w, ln_b,
                                  q1w, k1w, v1w, q2w, k2w, v2w,
                                  out_w, lnf_w, lnf_b, head_w, out);
}